// round 13
// baseline (speedup 1.0000x reference)
#include <cuda_runtime.h>
#include <cooperative_groups.h>
#include <cstdint>

namespace cg = cooperative_groups;

namespace {
constexpr int kB   = 256;
constexpr int kD   = 2048;
constexpr int kS   = 8;
constexpr int kOut = 1000;

constexpr int BM = 32;                 // rows per m-tile
constexpr int BN = 256;                // cols per block
constexpr int BK = 16;                 // K per pipeline stage
constexpr int NSPLIT = 32;
constexpr int KSPLIT = kD / NSPLIT;    // 64
constexpr int NSTG   = KSPLIT / BK;    // 4 stages per block
constexpr int MT = 4;                  // m-tiles per subject (covers counts <= 128)
constexpr int CLUSTER = 8;             // splits reduced per cluster via DSMEM
constexpr int NGROUP = NSPLIT / CLUSTER;  // 4 partial groups
constexpr int XPAD = 36;               // X k-row stride (16B multiple, bank skew)
constexpr int NTILES = (kOut + BN - 1) / BN;  // 4
}

// Device scratch: one partial per cluster-group (4 MB, stays L2-hot)
__device__ float g_partial[NGROUP * kB * kOut];

// ---- packed f32x2 helpers ----
__device__ __forceinline__ void ffma2(unsigned long long& d,
                                      unsigned long long a, unsigned long long b) {
    asm("fma.rn.f32x2 %0, %1, %2, %0;" : "+l"(d) : "l"(a), "l"(b));
}
__device__ __forceinline__ unsigned long long dup2(float v) {
    unsigned long long r;
    asm("mov.b64 %0, {%1, %1};" : "=l"(r) : "f"(v));
    return r;
}
__device__ __forceinline__ void unpack2(unsigned long long v, float& lo, float& hi) {
    asm("mov.b64 {%0, %1}, %2;" : "=f"(lo), "=f"(hi) : "l"(v));
}

// ---- cp.async helpers ----
__device__ __forceinline__ unsigned smem_u32(const void* p) {
    return (unsigned)__cvta_generic_to_shared(p);
}
__device__ __forceinline__ void cp16_ef(unsigned dst, const void* src, int src_sz,
                                        unsigned long long pol) {
    asm volatile("cp.async.cg.shared.global.L2::cache_hint [%0], [%1], 16, %2, %3;"
                 :: "r"(dst), "l"(src), "r"(src_sz), "l"(pol) : "memory");
}
__device__ __forceinline__ void cp_commit() {
    asm volatile("cp.async.commit_group;" ::: "memory");
}
__device__ __forceinline__ void cp_wait1() {
    asm volatile("cp.async.wait_group 1;" ::: "memory");
}

// ---------------------------------------------------------------------------
// GEMM + DSMEM split reduction.
// grid (ntile=4, subject=8, z=128), cluster (1,1,8): the 8 cluster CTAs are
// 8 adjacent K-splits of one (ntile, s, mt) tile. z = (group*MT + mt)*8 + sub,
// split = group*8 + sub. Mainloop identical to the measured 30.6us config.
// Epilogue: acc -> smem (reusing the 32KB Ws ring), cluster.sync, each rank
// sums its 1/8 of the tile across all 8 peers' DSMEM and stores ONE partial
// per cluster-group (plain STG, fixed order -> deterministic). Partials
// shrink 32MB -> 4MB, so the final reduce is L2-hot and tiny.
// ---------------------------------------------------------------------------
__global__ __launch_bounds__(128, 5) __cluster_dims__(1, 1, CLUSTER)
void gemm_kernel(
    const float* __restrict__ x,              // [B, D]
    const float* __restrict__ W,              // [S, D, OUT]
    const unsigned int* __restrict__ sid_words)
{
    const int s     = blockIdx.y;
    const int sub   = blockIdx.z & (CLUSTER - 1);     // split within cluster
    const int gm    = blockIdx.z >> 3;                // 0..15
    const int mt    = gm & (MT - 1);
    const int group = gm >> 2;                        // 0..3
    const int split = group * CLUSTER + sub;
    const int m0    = mt * BM;
    const int n0    = blockIdx.x * BN;
    const int kbase = split * KSPLIT;
    const int t     = threadIdx.x;
    const int lane  = t & 31;
    const int warp  = t >> 5;

    __shared__ __align__(16) float Xs[2][BK][XPAD];  // X tile [k][m]
    __shared__ __align__(16) float Ws[2][BK][BN];    // W ring; reused as 32x256 acc
    __shared__ int srows[BM];
    __shared__ int chunk_cnt[8];
    __shared__ int hi_flag;

    // ---- 4-warp parallel bucketing: ordered row list for subject s ----
    // int64-vs-int32 detection: for little-endian int64 ids in [0,8) all odd
    // 32-bit words of the first 256 words are zero.
    if (t < BM) srows[t] = -1;
    if (t == 0) hi_flag = 0;
    __syncthreads();

    const unsigned full = 0xFFFFFFFFu;
    const int b0 = (2 * warp) * 32 + lane;        // chunks 2w, 2w+1
    const int b1 = (2 * warp + 1) * 32 + lane;
    {
        const unsigned any_hi = sid_words[2 * b0 + 1] | sid_words[2 * b1 + 1];
        if (__any_sync(full, any_hi != 0u) && lane == 0) hi_flag = 1;
    }
    __syncthreads();
    const bool is_i32 = (hi_flag != 0);

    const int sb0 = is_i32 ? (int)sid_words[b0] : (int)sid_words[2 * b0];
    const int sb1 = is_i32 ? (int)sid_words[b1] : (int)sid_words[2 * b1];
    const unsigned msk0 = __ballot_sync(full, sb0 == s);
    const unsigned msk1 = __ballot_sync(full, sb1 == s);
    if (lane == 0) {
        chunk_cnt[2 * warp]     = __popc(msk0);
        chunk_cnt[2 * warp + 1] = __popc(msk1);
    }
    __syncthreads();

    int cnt = 0, base0 = 0;
    #pragma unroll
    for (int c = 0; c < 8; ++c) {
        if (c < 2 * warp) base0 += chunk_cnt[c];
        cnt += chunk_cnt[c];
    }
    // Uniform across the whole cluster (same s, mt) -> no barrier divergence.
    if (m0 >= cnt) return;
    const int base1 = base0 + chunk_cnt[2 * warp];
    const unsigned below = (1u << lane) - 1u;
    if (sb0 == s) {
        const int pos = base0 + __popc(msk0 & below);
        if (pos >= m0 && pos < m0 + BM) srows[pos - m0] = b0;
    }
    if (sb1 == s) {
        const int pos = base1 + __popc(msk1 & below);
        if (pos >= m0 && pos < m0 + BM) srows[pos - m0] = b1;
    }
    __syncthreads();

    // ---- L2 evict_first policy for the single-use W stream ----
    unsigned long long pol_ef;
    asm("createpolicy.fractional.L2::evict_first.b64 %0, 1.0;" : "=l"(pol_ef));

    // ---- W cp.async roles: 1024 16B chunks per stage, 8 per thread ----
    const int wn_   = (t & 63) * 4;        // col within tile (0..252)
    const int khalf = t >> 6;              // 0/1
    const float* wbase = W + ((size_t)s * kD + kbase) * kOut + n0 + wn_;
    const int wsz = (n0 + wn_ + 3 < kOut) ? 16 : 0;   // zero-fill OOB n-tail

    auto issueW = [&](int st) {
        if (st < NSTG) {
            const int buf = st & 1;
            const float* wsrc = wbase + (size_t)st * BK * kOut;
            #pragma unroll
            for (int q = 0; q < 8; ++q) {
                const int k = 2 * q + khalf;
                cp16_ef(smem_u32(&Ws[buf][k][wn_]), wsrc + (size_t)k * kOut, wsz, pol_ef);
            }
        }
        cp_commit();   // empty tail groups keep wait counts aligned
    };

    // ---- X roles: 128 k-quads per stage, 1 LDG.128 + 4 STS per thread ----
    const int xm_  = t >> 2;               // 0..31
    const int xk4  = (t & 3) * 4;          // k quad within stage
    const int xrow = srows[xm_];
    const float* xptr = (xrow >= 0) ? (x + (size_t)xrow * kD + kbase + xk4)
                                    : nullptr;
    float4 xr = make_float4(0.f, 0.f, 0.f, 0.f);

    issueW(0);
    issueW(1);
    if (xptr) xr = *reinterpret_cast<const float4*>(xptr);   // stage 0

    // ---- compute roles: rows [tm, tm+8); cols n0+ln..+3 and n0+128+ln..+3 ----
    const int tm = warp * 8;               // uniform per warp -> broadcast LDS
    const int ln = lane * 4;               // 16B lane stride -> conflict-free

    unsigned long long acc[8][4];          // [m][pairs: A0 A1 B0 B1]
    #pragma unroll
    for (int i = 0; i < 8; ++i)
        #pragma unroll
        for (int j = 0; j < 4; ++j) acc[i][j] = 0ull;

    #pragma unroll
    for (int st = 0; st < NSTG; ++st) {
        const int buf = st & 1;
        cp_wait1();                         // W(st) arrived
        // transpose-store X(st)
        Xs[buf][xk4 + 0][xm_] = xr.x;
        Xs[buf][xk4 + 1][xm_] = xr.y;
        Xs[buf][xk4 + 2][xm_] = xr.z;
        Xs[buf][xk4 + 3][xm_] = xr.w;
        __syncthreads();
        // prefetch X(st+1) into registers
        if (st + 1 < NSTG && xptr)
            xr = *reinterpret_cast<const float4*>(xptr + (st + 1) * BK);

        #pragma unroll
        for (int kk = 0; kk < BK; ++kk) {
            const float4 xa = *reinterpret_cast<const float4*>(&Xs[buf][kk][tm]);
            const float4 xb = *reinterpret_cast<const float4*>(&Xs[buf][kk][tm + 4]);
            const ulonglong2 wA = *reinterpret_cast<const ulonglong2*>(&Ws[buf][kk][ln]);
            const ulonglong2 wB = *reinterpret_cast<const ulonglong2*>(&Ws[buf][kk][128 + ln]);
            const unsigned long long dx[8] = {
                dup2(xa.x), dup2(xa.y), dup2(xa.z), dup2(xa.w),
                dup2(xb.x), dup2(xb.y), dup2(xb.z), dup2(xb.w)};
            #pragma unroll
            for (int i = 0; i < 8; ++i) {
                ffma2(acc[i][0], dx[i], wA.x);
                ffma2(acc[i][1], dx[i], wA.y);
                ffma2(acc[i][2], dx[i], wB.x);
                ffma2(acc[i][3], dx[i], wB.y);
            }
        }
        __syncthreads();                    // all reads of Ws[buf] done
        issueW(st + 2);                     // refill into Ws[buf]
    }

    // ---- epilogue: DSMEM cluster reduction over the 8 splits ----
    cg::cluster_group cluster = cg::this_cluster();

    // Park accumulators in the (now idle) Ws ring: [32 rows][256 cols] fp32.
    float* red = &Ws[0][0][0];             // exactly 32KB
    #pragma unroll
    for (int i = 0; i < 8; ++i) {
        float vA0, vA1, vA2, vA3, vB0, vB1, vB2, vB3;
        unpack2(acc[i][0], vA0, vA1);
        unpack2(acc[i][1], vA2, vA3);
        unpack2(acc[i][2], vB0, vB1);
        unpack2(acc[i][3], vB2, vB3);
        float* rr = red + (tm + i) * BN;
        *reinterpret_cast<float4*>(rr + ln)       = make_float4(vA0, vA1, vA2, vA3);
        *reinterpret_cast<float4*>(rr + 128 + ln) = make_float4(vB0, vB1, vB2, vB3);
    }
    cluster.sync();                        // acc tiles visible cluster-wide

    // Each rank sums its 1/8 of the 32x256 tile across all 8 peers (fixed
    // src order 0..7 -> deterministic) and stores one group-partial.
    const unsigned myrank = cluster.block_rank();
    float* pbase = g_partial + (size_t)group * kB * kOut;
    #pragma unroll
    for (int q = 0; q < 2; ++q) {
        const int fpos = (int)myrank * 256 + q * 128 + t;   // 0..2047 float4s
        const int row  = fpos >> 6;
        const int col  = (fpos & 63) * 4;
        float4 v = make_float4(0.f, 0.f, 0.f, 0.f);
        #pragma unroll
        for (int src = 0; src < CLUSTER; ++src) {
            const float4* p = reinterpret_cast<const float4*>(
                cluster.map_shared_rank(red + row * BN + col, src));
            const float4 a = *p;
            v.x += a.x; v.y += a.y; v.z += a.z; v.w += a.w;
        }
        const int r  = srows[row];
        const int gn = n0 + col;
        if (r >= 0 && gn + 3 < kOut)       // kOut%4==0: quad fully in or out
            *reinterpret_cast<float4*>(pbase + (size_t)r * kOut + gn) = v;
    }
    cluster.sync();                        // keep peer smem alive until read
}

// ---------------------------------------------------------------------------
// Reduce: out = sum of 4 group partials (L2-hot, 4 MB) + per-subject bias.
// ---------------------------------------------------------------------------
__global__ __launch_bounds__(256) void reduce_kernel(
    const unsigned int* __restrict__ sid_words,
    const float* __restrict__ bias,   // [S, OUT]
    float* __restrict__ out)          // [B, OUT]
{
    __shared__ int i32_flag;
    if (threadIdx.x == 0) i32_flag = 0;
    __syncthreads();
    if (threadIdx.x < 128 && sid_words[2 * threadIdx.x + 1] != 0u)
        atomicOr(&i32_flag, 1);
    __syncthreads();

    const int q = blockIdx.x * blockDim.x + threadIdx.x;
    const int base = q * 4;
    if (base >= kB * kOut) return;
    const int b = base / kOut;
    const int n = base - b * kOut;        // kOut % 4 == 0: quad stays in row
    const int sb = i32_flag ? (int)sid_words[b] : (int)sid_words[2 * b];

    float4 v = *reinterpret_cast<const float4*>(bias + (size_t)sb * kOut + n);
    #pragma unroll
    for (int g = 0; g < NGROUP; ++g) {
        const float4 p = *reinterpret_cast<const float4*>(
            g_partial + (size_t)g * kB * kOut + base);
        v.x += p.x; v.y += p.y; v.z += p.z; v.w += p.w;
    }
    *reinterpret_cast<float4*>(out + base) = v;
}

extern "C" void kernel_launch(void* const* d_in, const int* in_sizes, int n_in,
                              void* d_out, int out_size) {
    const float*        x   = (const float*)d_in[0];
    const unsigned int* sid = (const unsigned int*)d_in[1];
    const float*        W   = (const float*)d_in[2];
    const float*        b   = (const float*)d_in[3];
    float*              out = (float*)d_out;

    dim3 grid(NTILES, kS, MT * NSPLIT);   // (4, 8, 128); cluster (1,1,8)
    gemm_kernel<<<grid, 128>>>(x, W, sid);
    const int nq = (kB * kOut) / 4;       // 64000 quads
    reduce_kernel<<<(nq + 255) / 256, 256>>>(sid, b, out);
}

// round 15
// speedup vs baseline: 1.3265x; 1.3265x over previous
#include <cuda_runtime.h>
#include <cstdint>

namespace {
constexpr int kB   = 256;
constexpr int kD   = 2048;
constexpr int kS   = 8;
constexpr int kOut = 1000;

constexpr int BM = 32;                 // rows per m-tile
constexpr int BN = 128;                // cols per block (4 warps x 32n)
constexpr int BK = 32;                 // K per stage
constexpr int NSPLIT = 8;
constexpr int KSPLIT = kD / NSPLIT;    // 256
constexpr int NSTG   = KSPLIT / BK;    // 8 stages
constexpr int MT = 4;                  // m-tiles per subject (covers counts <= 128)
constexpr int NTILES = (kOut + BN - 1) / BN;  // 8
}

// Device scratch (allocations forbidden in kernel_launch)
__device__ float g_partial[NSPLIT * kB * kOut];   // 8 MB

// ---- helpers ----
__device__ __forceinline__ unsigned smem_u32(const void* p) {
    return (unsigned)__cvta_generic_to_shared(p);
}
// SW64 swizzle for 64-byte rows (8 rows x 64B atom): XOR 16B-chunk bits with row bits.
__device__ __forceinline__ unsigned sw64(unsigned off) {
    return off ^ ((off >> 3) & 0x30u);
}
// hi = truncate-to-bf16 (byte_perm), lo = bf16_rn(v - hi): dropped term <= ~2^-16.
__device__ __forceinline__ void cvt_pair(float a, float b,
                                         unsigned& hi, unsigned& lo) {
    const unsigned ua = __float_as_uint(a), ub = __float_as_uint(b);
    hi = __byte_perm(ua, ub, 0x7632);          // {bf16(a) low, bf16(b) high}
    const float ra = a - __uint_as_float(ua & 0xFFFF0000u);
    const float rb = b - __uint_as_float(ub & 0xFFFF0000u);
    asm("cvt.rn.bf16x2.f32 %0, %1, %2;" : "=r"(lo) : "f"(rb), "f"(ra));
}
__device__ __forceinline__ void ldsm4(unsigned& r0, unsigned& r1,
                                      unsigned& r2, unsigned& r3, unsigned addr) {
    asm volatile("ldmatrix.sync.aligned.m8n8.x4.shared.b16 {%0,%1,%2,%3}, [%4];"
                 : "=r"(r0), "=r"(r1), "=r"(r2), "=r"(r3) : "r"(addr));
}
__device__ __forceinline__ void mma_bf16(float* c, const unsigned* a,
                                         unsigned b0, unsigned b1) {
    asm volatile(
        "mma.sync.aligned.m16n8k16.row.col.f32.bf16.bf16.f32 "
        "{%0,%1,%2,%3}, {%4,%5,%6,%7}, {%8,%9}, {%0,%1,%2,%3};"
        : "+f"(c[0]), "+f"(c[1]), "+f"(c[2]), "+f"(c[3])
        : "r"(a[0]), "r"(a[1]), "r"(a[2]), "r"(a[3]), "r"(b0), "r"(b1));
}

// ---------------------------------------------------------------------------
// HMMA GEMM: grid (ntile=8, subject=8, mt(4)*split(8)=32), 128 threads.
// Per block: D[32m x 128n] over K=256 via bf16 hi/lo 3-pass mma.sync.
// A = gathered x rows (hi/lo bf16, [m][32k] SW64); B = W columns transposed
// during staging ([n][32k] SW64). Fragments via ldmatrix.x4; fp32 register
// accumulators; epilogue writes split partials (reduce adds bias).
// ---------------------------------------------------------------------------
__global__ __launch_bounds__(128) void gemm_hmma_kernel(
    const float* __restrict__ x,              // [B, D]
    const float* __restrict__ W,              // [S, D, OUT]
    const unsigned int* __restrict__ sid_words)
{
    const int ntile = blockIdx.x;
    const int s     = blockIdx.y;
    const int mt    = blockIdx.z & (MT - 1);
    const int split = blockIdx.z >> 2;        // MT = 4
    const int m0    = mt * BM;
    const int n0    = ntile * BN;
    const int kbase = split * KSPLIT;
    const int t     = threadIdx.x;
    const int lane  = t & 31;
    const int warp  = t >> 5;

    __shared__ __align__(1024) unsigned char sAhi[BM * 64];   // [32 m][32 bf16]
    __shared__ __align__(1024) unsigned char sAlo[BM * 64];
    __shared__ __align__(1024) unsigned char sBhi[BN * 64];   // [128 n][32 bf16]
    __shared__ __align__(1024) unsigned char sBlo[BN * 64];
    __shared__ int srows[BM];
    __shared__ int chunk_cnt[8];
    __shared__ int hi_flag;

    // ---- 4-warp parallel bucketing: ordered row list for subject s ----
    // int64-vs-int32 detection: for little-endian int64 ids in [0,8) all odd
    // 32-bit words of the first 256 words are zero.
    if (t < BM) srows[t] = -1;
    if (t == 0) hi_flag = 0;
    __syncthreads();

    const unsigned full = 0xFFFFFFFFu;
    const int b0 = (2 * warp) * 32 + lane;
    const int b1 = (2 * warp + 1) * 32 + lane;
    {
        const unsigned any_hi = sid_words[2 * b0 + 1] | sid_words[2 * b1 + 1];
        if (__any_sync(full, any_hi != 0u) && lane == 0) hi_flag = 1;
    }
    __syncthreads();
    const bool is_i32 = (hi_flag != 0);

    const int sb0 = is_i32 ? (int)sid_words[b0] : (int)sid_words[2 * b0];
    const int sb1 = is_i32 ? (int)sid_words[b1] : (int)sid_words[2 * b1];
    const unsigned msk0 = __ballot_sync(full, sb0 == s);
    const unsigned msk1 = __ballot_sync(full, sb1 == s);
    if (lane == 0) {
        chunk_cnt[2 * warp]     = __popc(msk0);
        chunk_cnt[2 * warp + 1] = __popc(msk1);
    }
    __syncthreads();

    int cnt = 0, base0 = 0;
    #pragma unroll
    for (int c = 0; c < 8; ++c) {
        if (c < 2 * warp) base0 += chunk_cnt[c];
        cnt += chunk_cnt[c];
    }
    if (m0 >= cnt) return;                    // uniform exit for empty tiles
    const int base1 = base0 + chunk_cnt[2 * warp];
    const unsigned below = (1u << lane) - 1u;
    if (sb0 == s) {
        const int pos = base0 + __popc(msk0 & below);
        if (pos >= m0 && pos < m0 + BM) srows[pos - m0] = b0;
    }
    if (sb1 == s) {
        const int pos = base1 + __popc(msk1 & below);
        if (pos >= m0 && pos < m0 + BM) srows[pos - m0] = b1;
    }
    __syncthreads();

    // ---- staging roles ----
    // A: thread t -> row m = t>>2, k-octet (t&3)*8. 8 floats -> one 16B hi + lo chunk.
    const int am  = t >> 2;
    const int akq = (t & 3) * 8;
    const int arow = srows[am];
    const float* xptr = (arow >= 0) ? (x + (size_t)arow * kD + kbase + akq) : nullptr;
    const unsigned aoff = sw64((unsigned)(am * 64 + (akq >> 3) * 16));

    // B: thread t -> column n = n0 + t; reads down W column (coalesced across
    // lanes), stores transposed K-major.
    const bool nvalid = (n0 + t) < kOut;
    const int  nn     = nvalid ? (n0 + t) : (kOut - 1);
    const float* wcol = W + ((size_t)s * kD + kbase) * kOut + nn;

    const unsigned aHi = smem_u32(sAhi), aLo = smem_u32(sAlo);
    const unsigned bHi = smem_u32(sBhi), bLo = smem_u32(sBlo);

    float acc[2][4][4];                       // [mfrag][nfrag][c0..c3]
    #pragma unroll
    for (int i = 0; i < 2; ++i)
        #pragma unroll
        for (int j = 0; j < 4; ++j)
            #pragma unroll
            for (int q = 0; q < 4; ++q) acc[i][j][q] = 0.f;

    for (int st = 0; st < NSTG; ++st) {
        // ---- stage A ----
        {
            float4 v0 = make_float4(0.f, 0.f, 0.f, 0.f), v1 = v0;
            if (xptr) {
                const float4* xs = reinterpret_cast<const float4*>(xptr + st * BK);
                v0 = xs[0]; v1 = xs[1];
            }
            unsigned h0, l0, h1, l1, h2, l2, h3, l3;
            cvt_pair(v0.x, v0.y, h0, l0);
            cvt_pair(v0.z, v0.w, h1, l1);
            cvt_pair(v1.x, v1.y, h2, l2);
            cvt_pair(v1.z, v1.w, h3, l3);
            *reinterpret_cast<uint4*>(sAhi + aoff) = make_uint4(h0, h1, h2, h3);
            *reinterpret_cast<uint4*>(sAlo + aoff) = make_uint4(l0, l1, l2, l3);
        }
        // ---- stage B (transpose 32 k-values down column n) ----
        #pragma unroll
        for (int j = 0; j < 8; ++j) {
            float w0 = 0.f, w1 = 0.f, w2 = 0.f, w3 = 0.f;
            if (nvalid) {
                const float* p = wcol + (size_t)(st * BK + j * 4) * kOut;
                w0 = p[0];
                w1 = p[kOut];
                w2 = p[2 * (size_t)kOut];
                w3 = p[3 * (size_t)kOut];
            }
            unsigned h0, l0, h1, l1;
            cvt_pair(w0, w1, h0, l0);
            cvt_pair(w2, w3, h1, l1);
            const unsigned boff = sw64((unsigned)(t * 64 + j * 8));
            *reinterpret_cast<uint2*>(sBhi + boff) = make_uint2(h0, h1);
            *reinterpret_cast<uint2*>(sBlo + boff) = make_uint2(l0, l1);
        }
        __syncthreads();

        // ---- consume: 2 k16-steps, 3 hi/lo passes each ----
        #pragma unroll
        for (int ks = 0; ks < 2; ++ks) {
            const int kc0 = ks * 2;
            unsigned Ah[2][4], Al[2][4], Bh[2][4], Bl[2][4];
            // A fragments (m16k16 x2)
            #pragma unroll
            for (int f = 0; f < 2; ++f) {
                const int i = lane >> 3, r = lane & 7;
                const int m  = f * 16 + ((i & 1) << 3) + r;
                const int kc = kc0 + (i >> 1);
                const unsigned off = sw64((unsigned)(m * 64 + kc * 16));
                ldsm4(Ah[f][0], Ah[f][1], Ah[f][2], Ah[f][3], aHi + off);
                ldsm4(Al[f][0], Al[f][1], Al[f][2], Al[f][3], aLo + off);
            }
            // B fragments (two x4 loads cover 4 n8-frags x k16)
            #pragma unroll
            for (int p = 0; p < 2; ++p) {
                const int i = lane >> 3, r = lane & 7;
                const int n  = warp * 32 + p * 16 + ((i >> 1) << 3) + r;
                const int kc = kc0 + (i & 1);
                const unsigned off = sw64((unsigned)(n * 64 + kc * 16));
                ldsm4(Bh[p][0], Bh[p][1], Bh[p][2], Bh[p][3], bHi + off);
                ldsm4(Bl[p][0], Bl[p][1], Bl[p][2], Bl[p][3], bLo + off);
            }
            #pragma unroll
            for (int mf = 0; mf < 2; ++mf) {
                #pragma unroll
                for (int nf = 0; nf < 4; ++nf) {
                    const int p = nf >> 1, q = (nf & 1) * 2;
                    mma_bf16(acc[mf][nf], Ah[mf], Bh[p][q], Bh[p][q + 1]);
                    mma_bf16(acc[mf][nf], Ah[mf], Bl[p][q], Bl[p][q + 1]);
                    mma_bf16(acc[mf][nf], Al[mf], Bh[p][q], Bh[p][q + 1]);
                }
            }
        }
        __syncthreads();                      // tiles consumed; safe to overwrite
    }

    // ---- epilogue: scatter split partials ----
    const int gid = lane >> 2, tid = lane & 3;
    float* pb = g_partial + (size_t)split * kB * kOut;
    #pragma unroll
    for (int mf = 0; mf < 2; ++mf) {
        const int r0 = srows[mf * 16 + gid];
        const int r1 = srows[mf * 16 + gid + 8];
        #pragma unroll
        for (int nf = 0; nf < 4; ++nf) {
            const int n = n0 + warp * 32 + nf * 8 + tid * 2;
            if (n + 1 >= kOut) continue;      // n even, kOut even: pair in or out
            if (r0 >= 0)
                *reinterpret_cast<float2*>(pb + (size_t)r0 * kOut + n) =
                    make_float2(acc[mf][nf][0], acc[mf][nf][1]);
            if (r1 >= 0)
                *reinterpret_cast<float2*>(pb + (size_t)r1 * kOut + n) =
                    make_float2(acc[mf][nf][2], acc[mf][nf][3]);
        }
    }
}

// ---------------------------------------------------------------------------
// Reduce: out = sum of 8 split partials + per-subject bias (float4).
// ---------------------------------------------------------------------------
__global__ __launch_bounds__(256) void reduce_kernel(
    const unsigned int* __restrict__ sid_words,
    const float* __restrict__ bias,   // [S, OUT]
    float* __restrict__ out)          // [B, OUT]
{
    __shared__ int i32_flag;
    if (threadIdx.x == 0) i32_flag = 0;
    __syncthreads();
    if (threadIdx.x < 128 && sid_words[2 * threadIdx.x + 1] != 0u)
        atomicOr(&i32_flag, 1);
    __syncthreads();

    const int q = blockIdx.x * blockDim.x + threadIdx.x;
    const int base = q * 4;
    if (base >= kB * kOut) return;
    const int b = base / kOut;
    const int n = base - b * kOut;        // kOut % 4 == 0: quad stays in row
    const int sb = i32_flag ? (int)sid_words[b] : (int)sid_words[2 * b];

    float4 v = *reinterpret_cast<const float4*>(bias + (size_t)sb * kOut + n);
    #pragma unroll
    for (int sp = 0; sp < NSPLIT; ++sp) {
        const float4 p = *reinterpret_cast<const float4*>(
            g_partial + (size_t)sp * kB * kOut + base);
        v.x += p.x; v.y += p.y; v.z += p.z; v.w += p.w;
    }
    *reinterpret_cast<float4*>(out + base) = v;
}

extern "C" void kernel_launch(void* const* d_in, const int* in_sizes, int n_in,
                              void* d_out, int out_size) {
    const float*        x   = (const float*)d_in[0];
    const unsigned int* sid = (const unsigned int*)d_in[1];
    const float*        W   = (const float*)d_in[2];
    const float*        b   = (const float*)d_in[3];
    float*              out = (float*)d_out;

    dim3 grid(NTILES, kS, MT * NSPLIT);   // (8, 8, 32)
    gemm_hmma_kernel<<<grid, 128>>>(x, W, sid);
    const int nq = (kB * kOut) / 4;       // 64000 quads
    reduce_kernel<<<(nq + 255) / 256, 256>>>(sid, b, out);
}